// round 16
// baseline (speedup 1.0000x reference)
#include <cuda_runtime.h>
#include <cuda_fp16.h>
#include <math.h>
#include <stdint.h>

#define NP 65536
#define CDIM 180
#define NHEADS 6
#define HD 30
#define HID 720
#define KP1 192
#define KP2 768
#define PW 258   // padded image width/height

// ---------------- scratch (device globals; no allocations) ----------------
__device__ __align__(16) float g_qkv[NP * 540];
__device__ __align__(16) float g_proj[NP * CDIM];
__device__ __align__(16) float g_y2[NP * CDIM];
__device__ __align__(16) __half g_rpbb[NHEADS * 65536];
__device__ float g_casum[CDIM];
__device__ float g_ca[CDIM];
__device__ __align__(16) float g_x1[NP * CDIM];
// padded fp16 image for conv branch (halo stays zero forever)
__device__ __align__(16) __half g_xnp[PW * PW * KP1];
__device__ __align__(16) __half g_y1p[PW * PW * 64];
// fp16 split activations (zero-initialized; K-pad columns stay zero forever)
__device__ __align__(16) __half g_ahi[NP * KP1];
__device__ __align__(16) __half g_alo[NP * KP1];
__device__ __align__(16) __half g_mhi[NP * KP2];
__device__ __align__(16) __half g_mlo[NP * KP2];
// fp16 transposed weights [N_pad][K_pad]
__device__ __align__(16) __half g_bqh[576 * KP1];
__device__ __align__(16) __half g_bph[192 * KP1];
__device__ __align__(16) __half g_b1h[768 * KP1];
__device__ __align__(16) __half g_b2h[192 * KP2];
// conv weights: [tap][ocpad][kpad] fp16
__device__ __align__(16) __half g_wc1h[9 * 64 * KP1];
__device__ __align__(16) __half g_wc2h[9 * 192 * 64];

// streams/events created pre-main (static init) so no allocations inside kernel_launch
namespace {
struct Aux {
    cudaStream_t s2;
    cudaEvent_t ev0, ev1;
    Aux() {
        cudaStreamCreateWithFlags(&s2, cudaStreamNonBlocking);
        cudaEventCreateWithFlags(&ev0, cudaEventDisableTiming);
        cudaEventCreateWithFlags(&ev1, cudaEventDisableTiming);
    }
};
Aux g_aux;
}

__device__ __forceinline__ float gelu_f(float x) {
    return 0.5f * x * (1.0f + erff(x * 0.70710678118654752f));
}
__device__ __forceinline__ float warp_sum(float v) {
    for (int o = 16; o > 0; o >>= 1) v += __shfl_xor_sync(0xffffffffu, v, o);
    return v;
}
__device__ __forceinline__ void store_hilo(__half* h, __half* l, size_t idx, float v) {
    __half hh = __float2half_rn(v);
    h[idx] = hh;
    l[idx] = __float2half_rn(v - __half2float(hh));
}
__device__ __forceinline__ uint32_t smem_u32(const void* p) {
    uint32_t a;
    asm("{ .reg .u64 t; cvta.to.shared.u64 t, %1; cvt.u32.u64 %0, t; }" : "=r"(a) : "l"(p));
    return a;
}
__device__ __forceinline__ void ldsm_x4(uint32_t& r0, uint32_t& r1, uint32_t& r2, uint32_t& r3,
                                        uint32_t addr) {
    asm volatile("ldmatrix.sync.aligned.m8n8.x4.shared.b16 {%0,%1,%2,%3}, [%4];"
                 : "=r"(r0), "=r"(r1), "=r"(r2), "=r"(r3) : "r"(addr));
}
__device__ __forceinline__ void mma_f16(float* c, const uint32_t* a, const uint32_t* b) {
    asm volatile(
        "mma.sync.aligned.m16n8k16.row.col.f32.f16.f16.f32 "
        "{%0,%1,%2,%3}, {%4,%5,%6,%7}, {%8,%9}, {%0,%1,%2,%3};"
        : "+f"(c[0]), "+f"(c[1]), "+f"(c[2]), "+f"(c[3])
        : "r"(a[0]), "r"(a[1]), "r"(a[2]), "r"(a[3]), "r"(b[0]), "r"(b[1]));
}
__device__ __forceinline__ void split2(float a, float b, uint32_t& hi, uint32_t& lo) {
    __half ah = __float2half_rn(a), bh = __float2half_rn(b);
    __half2 h2; h2.x = ah; h2.y = bh;
    hi = *(uint32_t*)&h2;
    __half2 l2;
    l2.x = __float2half_rn(a - __half2float(ah));
    l2.y = __float2half_rn(b - __half2float(bh));
    lo = *(uint32_t*)&l2;
}
__device__ __forceinline__ void cp16(uint32_t s, const void* g) {
    asm volatile("cp.async.cg.shared.global [%0], [%1], 16;" :: "r"(s), "l"(g));
}
#define CP_COMMIT asm volatile("cp.async.commit_group;")
#define CP_WAIT0 asm volatile("cp.async.wait_group 0;" ::: "memory")

// ---------------- merged weight prep + rpb + casum zero (one launch) ----------------
__global__ void mega_prep(const float* __restrict__ qkvw, const float* __restrict__ projw,
                          const float* __restrict__ f1w, const float* __restrict__ f2w,
                          const float* __restrict__ c1w, const float* __restrict__ c2w,
                          const int* __restrict__ rpi, const float* __restrict__ rpbt,
                          __half* __restrict__ bqh, __half* __restrict__ bph,
                          __half* __restrict__ b1h, __half* __restrict__ b2h,
                          __half* __restrict__ wc1h, __half* __restrict__ wc2h,
                          __half* __restrict__ rpbb, float* __restrict__ casum) {
    int b = blockIdx.x, t = threadIdx.x;
    if (b < 432) {
        int idx = b * 256 + t;
        if (idx < 576 * 192) {
            int n = idx / 192, k = idx % 192;
            bqh[idx] = __float2half_rn((n < 540 && k < 180) ? qkvw[k * 540 + n] : 0.f);
        }
    } else if (b < 576) {
        int idx = (b - 432) * 256 + t;
        if (idx < 192 * 192) {
            int n = idx / 192, k = idx % 192;
            bph[idx] = __float2half_rn((n < 180 && k < 180) ? projw[k * 180 + n] : 0.f);
        }
    } else if (b < 1152) {
        int idx = (b - 576) * 256 + t;
        if (idx < 768 * 192) {
            int n = idx / 192, k = idx % 192;
            b1h[idx] = __float2half_rn((n < 720 && k < 180) ? f1w[k * 720 + n] : 0.f);
        }
    } else if (b < 1728) {
        int idx = (b - 1152) * 256 + t;
        if (idx < 192 * 768) {
            int n = idx / 768, k = idx % 768;
            b2h[idx] = __float2half_rn((n < 180 && k < 720) ? f2w[k * 180 + n] : 0.f);
        }
    } else if (b < 2160) {
        int idx = (b - 1728) * 256 + t;
        if (idx < 9 * 64 * KP1) {
            int k = idx % KP1;
            int rest = idx / KP1;
            int oc = rest % 64, tap = rest / 64;
            wc1h[idx] = __float2half_rn((oc < 60 && k < 180) ? c1w[(oc * 180 + k) * 9 + tap] : 0.f);
        }
    } else if (b < 2592) {
        int idx = (b - 2160) * 256 + t;
        if (idx < 9 * 192 * 64) {
            int k = idx % 64;
            int rest = idx / 64;
            int oc = rest % 192, tap = rest / 192;
            wc2h[idx] = __float2half_rn((oc < 180 && k < 60) ? c2w[(oc * 60 + k) * 9 + tap] : 0.f);
        }
    } else if (b < 2848) {
        int idx = (b - 2592) * 256 + t;
        int r = rpi[idx];
#pragma unroll
        for (int h = 0; h < NHEADS; h++)
            rpbb[h * 65536 + idx] = __float2half_rn(rpbt[r * NHEADS + h]);
    } else {
        if (t < CDIM) casum[t] = 0.f;
    }
}

// ---------------- persistent-A GEMM (Kpad=192), fused 2-pass fp16, pipelined B ----------------
#define LDA2 200
#define G2_A_ELEMS (128 * LDA2)
#define G2_B_ELEMS (64 * LDA2)
#define G2_SMEM ((2 * G2_A_ELEMS + 2 * G2_B_ELEMS) * 2)

template <int EPI>
__global__ void __launch_bounds__(256) tc_gemm2(
    const __half* __restrict__ Ahi, const __half* __restrict__ Alo,
    const __half* __restrict__ Bh,
    const float* __restrict__ bias,
    float* __restrict__ Cf, __half* __restrict__ Chi, __half* __restrict__ Clo,
    int Nvalid, int ldc, int ntiles) {
    extern __shared__ __align__(16) char sm2[];
    __half* sAh = (__half*)sm2;
    __half* sAl = sAh + G2_A_ELEMS;
    __half* sB = sAl + G2_A_ELEMS;
    const uint32_t sAhu = smem_u32(sAh), sAlu = smem_u32(sAl);
    const uint32_t sBu = smem_u32(sB);
    const int tid = threadIdx.x, wid = tid >> 5, lane = tid & 31;
    const int wm = wid >> 1, wn = wid & 1;
    const int m0 = blockIdx.x * 128;
    const int a_row = lane & 15, a_koff = (lane >> 4) << 3;
    const int b_grp = lane >> 3, b_n = ((b_grp & 1) << 3) + (lane & 7), b_koff = (b_grp >> 1) << 3;
    const int r_in = lane >> 2, c_in = (lane & 3) << 1;

#pragma unroll
    for (int it = 0; it < 12; it++) {
        int c = tid + it * 256;
        int rr = c / 24, ko = (c % 24) * 8;
        size_t ga = (size_t)(m0 + rr) * KP1 + ko;
        cp16(sAhu + (rr * LDA2 + ko) * 2, Ahi + ga);
        cp16(sAlu + (rr * LDA2 + ko) * 2, Alo + ga);
    }
#pragma unroll
    for (int it = 0; it < 6; it++) {
        int c = tid + it * 256;
        int rr = c / 24, ko = (c % 24) * 8;
        cp16(sBu + (rr * LDA2 + ko) * 2, Bh + (size_t)rr * KP1 + ko);
    }
    CP_COMMIT;

    for (int nt = 0; nt < ntiles; nt++) {
        const int n0 = nt * 64;
        CP_WAIT0;
        __syncthreads();
        if (nt + 1 < ntiles) {
            const uint32_t dst = sBu + (((nt + 1) & 1) * G2_B_ELEMS) * 2;
            const int nn0 = (nt + 1) * 64;
#pragma unroll
            for (int it = 0; it < 6; it++) {
                int c = tid + it * 256;
                int rr = c / 24, ko = (c % 24) * 8;
                cp16(dst + (rr * LDA2 + ko) * 2, Bh + (size_t)(nn0 + rr) * KP1 + ko);
            }
            CP_COMMIT;
        }
        const uint32_t bufH = sBu + ((nt & 1) * G2_B_ELEMS) * 2;

        float acc[2][4][4] = {};
        // fused hi/lo passes: load B fragments once per k-slice
#pragma unroll
        for (int ks = 0; ks < 12; ks++) {
            uint32_t ah[2][4], al[2][4], b[2][4];
#pragma unroll
            for (int mt = 0; mt < 2; mt++) {
                uint32_t off = (uint32_t)((wm * 32 + mt * 16 + a_row) * (LDA2 * 2) +
                                          (ks * 16 + a_koff) * 2);
                ldsm_x4(ah[mt][0], ah[mt][1], ah[mt][2], ah[mt][3], sAhu + off);
                ldsm_x4(al[mt][0], al[mt][1], al[mt][2], al[mt][3], sAlu + off);
            }
#pragma unroll
            for (int np = 0; np < 2; np++) {
                uint32_t bd = bufH +
                    (uint32_t)((wn * 32 + np * 16 + b_n) * (LDA2 * 2) +
                               (ks * 16 + b_koff) * 2);
                ldsm_x4(b[np][0], b[np][1], b[np][2], b[np][3], bd);
            }
#pragma unroll
            for (int mt = 0; mt < 2; mt++) {
#pragma unroll
                for (int np = 0; np < 2; np++) {
                    uint32_t f0[2] = { b[np][0], b[np][2] };
                    uint32_t f1[2] = { b[np][1], b[np][3] };
                    mma_f16(acc[mt][2 * np + 0], ah[mt], f0);
                    mma_f16(acc[mt][2 * np + 1], ah[mt], f1);
                    mma_f16(acc[mt][2 * np + 0], al[mt], f0);
                    mma_f16(acc[mt][2 * np + 1], al[mt], f1);
                }
            }
        }
#pragma unroll
        for (int mt = 0; mt < 2; mt++) {
            int mrow = m0 + wm * 32 + mt * 16 + r_in;
#pragma unroll
            for (int ntb = 0; ntb < 4; ntb++) {
                int col = n0 + wn * 32 + ntb * 8 + c_in;
#pragma unroll
                for (int e = 0; e < 4; e++) {
                    int rr = mrow + ((e >> 1) << 3);
                    int cc = col + (e & 1);
                    if (cc < Nvalid) {
                        float v = acc[mt][ntb][e] + bias[cc];
                        if (EPI == 0) {
                            Cf[(size_t)rr * ldc + cc] = v;
                        } else {
                            store_hilo(Chi, Clo, (size_t)rr * ldc + cc, gelu_f(v));
                        }
                    }
                }
            }
        }
    }
}

// ---------------- fc2: persistent accumulators, fused 2-pass fp16 ----------------
#define MLDA 72
#define MLP_A_ELEMS (128 * MLDA)
#define MLP_B_ELEMS (192 * MLDA)
#define MLP_BUF (2 * MLP_A_ELEMS + MLP_B_ELEMS)
#define MLP_SMEM (2 * MLP_BUF * 2)

__global__ void __launch_bounds__(256, 1) tc_mlp2(
    const __half* __restrict__ Ahi, const __half* __restrict__ Alo,
    const __half* __restrict__ Bh,
    const float* __restrict__ bias, const float* __restrict__ res,
    float* __restrict__ Cf) {
    extern __shared__ __align__(16) char smm[];
    const uint32_t smu = smem_u32(smm);
    const int tid = threadIdx.x, wid = tid >> 5, lane = tid & 31;
    const int wm = wid >> 1, wn = wid & 1;
    const int m0 = blockIdx.x * 128;
    const int a_row = lane & 15, a_koff = (lane >> 4) << 3;
    const int b_grp = lane >> 3, b_n = ((b_grp & 1) << 3) + (lane & 7), b_koff = (b_grp >> 1) << 3;
    const int r_in = lane >> 2, c_in = (lane & 3) << 1;

    {
        const uint32_t aH = smu, aL = smu + MLP_A_ELEMS * 2;
        const uint32_t bH = smu + 2 * MLP_A_ELEMS * 2;
#pragma unroll
        for (int it = 0; it < 4; it++) {
            int c = tid + it * 256;
            int rr = c >> 3, ko = (c & 7) * 8;
            size_t ga = (size_t)(m0 + rr) * KP2 + ko;
            cp16(aH + (rr * MLDA + ko) * 2, Ahi + ga);
            cp16(aL + (rr * MLDA + ko) * 2, Alo + ga);
        }
#pragma unroll
        for (int it = 0; it < 6; it++) {
            int c = tid + it * 256;
            int rr = c >> 3, ko = (c & 7) * 8;
            cp16(bH + (rr * MLDA + ko) * 2, Bh + (size_t)rr * KP2 + ko);
        }
        CP_COMMIT;
    }

    float acc[3][2][4][4] = {};

    for (int kc = 0; kc < 12; kc++) {
        CP_WAIT0;
        __syncthreads();
        if (kc + 1 < 12) {
            const uint32_t base = smu + (((kc + 1) & 1) * MLP_BUF) * 2;
            const uint32_t aH = base, aL = base + MLP_A_ELEMS * 2;
            const uint32_t bH = base + 2 * MLP_A_ELEMS * 2;
            const int k0 = (kc + 1) * 64;
#pragma unroll
            for (int it = 0; it < 4; it++) {
                int c = tid + it * 256;
                int rr = c >> 3, ko = (c & 7) * 8;
                size_t ga = (size_t)(m0 + rr) * KP2 + k0 + ko;
                cp16(aH + (rr * MLDA + ko) * 2, Ahi + ga);
                cp16(aL + (rr * MLDA + ko) * 2, Alo + ga);
            }
#pragma unroll
            for (int it = 0; it < 6; it++) {
                int c = tid + it * 256;
                int rr = c >> 3, ko = (c & 7) * 8;
                cp16(bH + (rr * MLDA + ko) * 2, Bh + (size_t)rr * KP2 + k0 + ko);
            }
            CP_COMMIT;
        }
        const uint32_t base = smu + ((kc & 1) * MLP_BUF) * 2;
        const uint32_t aH = base, aL = base + MLP_A_ELEMS * 2;
        const uint32_t bH = base + 2 * MLP_A_ELEMS * 2;

        // fused hi/lo: load A hi+lo once per k-slice, B once per (t, k-slice)
#pragma unroll
        for (int ks = 0; ks < 4; ks++) {
            uint32_t ah[2][4], al[2][4];
#pragma unroll
            for (int mt = 0; mt < 2; mt++) {
                uint32_t off = (uint32_t)((wm * 32 + mt * 16 + a_row) * (MLDA * 2) +
                                          (ks * 16 + a_koff) * 2);
                ldsm_x4(ah[mt][0], ah[mt][1], ah[mt][2], ah[mt][3], aH + off);
                ldsm_x4(al[mt][0], al[mt][1], al[mt][2], al[mt][3], aL + off);
            }
#pragma unroll
            for (int t = 0; t < 3; t++) {
                uint32_t b[2][4];
#pragma unroll
                for (int np = 0; np < 2; np++) {
                    uint32_t bd = bH +
                        (uint32_t)((t * 64 + wn * 32 + np * 16 + b_n) * (MLDA * 2) +
                                   (ks * 16 + b_koff) * 2);
                    ldsm_x4(b[np][0], b[np][1], b[np][2], b[np][3], bd);
                }
#pragma unroll
                for (int mt = 0; mt < 2; mt++) {
#pragma unroll
                    for (int np = 0; np < 2; np++) {
                        uint32_t f0[2] = { b[np][0], b[np][2] };
                        uint32_t f1[2] = { b[np][1], b[np][3] };
                        mma_f16(acc[t][mt][2 * np + 0], ah[mt], f0);
                        mma_f16(acc[t][mt][2 * np + 1], ah[mt], f1);
                        mma_f16(acc[t][mt][2 * np + 0], al[mt], f0);
                        mma_f16(acc[t][mt][2 * np + 1], al[mt], f1);
                    }
                }
            }
        }
    }

#pragma unroll
    for (int t = 0; t < 3; t++) {
#pragma unroll
        for (int mt = 0; mt < 2; mt++) {
            int mrow = m0 + wm * 32 + mt * 16 + r_in;
#pragma unroll
            for (int nt = 0; nt < 4; nt++) {
                int col = t * 64 + wn * 32 + nt * 8 + c_in;
#pragma unroll
                for (int e = 0; e < 4; e++) {
                    int rr = mrow + ((e >> 1) << 3);
                    int cc = col + (e & 1);
                    if (cc < CDIM) {
                        Cf[(size_t)rr * CDIM + cc] =
                            acc[t][mt][nt][e] + bias[cc] + res[(size_t)rr * CDIM + cc];
                    }
                }
            }
        }
    }
}

// ---------------- conv1: single-pass fp16 (high occupancy) ----------------
#define LDA 72
__global__ void __launch_bounds__(256) conv1_tc(
    const __half* __restrict__ xnp, const __half* __restrict__ wh,
    const float* __restrict__ bias, __half* __restrict__ y1p) {
    __shared__ __align__(16) __half sA[128 * LDA];
    __shared__ __align__(16) __half sB[64 * LDA];
    const uint32_t sAu = smem_u32(sA), sBu = smem_u32(sB);
    const int tid = threadIdx.x, wid = tid >> 5, lane = tid & 31;
    const int wm = wid >> 1, wn = wid & 1;
    const int tile = blockIdx.x;
    const int r = tile >> 1, c0 = (tile & 1) << 7;
    const int base = (r + 1) * PW + c0 + 1;
    const int a_row = lane & 15, a_koff = (lane >> 4) << 3;
    const int b_grp = lane >> 3, b_n = ((b_grp & 1) << 3) + (lane & 7), b_koff = (b_grp >> 1) << 3;
    float acc[2][4][4] = {};

    for (int tap = 0; tap < 9; tap++) {
        int dy = tap / 3 - 1, dx = tap % 3 - 1;
        int off = dy * PW + dx;
        for (int ch = 0; ch < 3; ch++) {
            __syncthreads();
#pragma unroll
            for (int it = 0; it < 4; it++) {
                int c = tid + it * 256;
                int rr = c >> 3, ko = (c & 7) << 3;
                *(uint4*)(sA + rr * LDA + ko) =
                    *(const uint4*)(xnp + (size_t)(base + off + rr) * KP1 + ch * 64 + ko);
            }
#pragma unroll
            for (int it = 0; it < 2; it++) {
                int c = tid + it * 256;
                int rr = c >> 3, ko = (c & 7) << 3;
                *(uint4*)(sB + rr * LDA + ko) =
                    *(const uint4*)(wh + (size_t)(tap * 64 + rr) * KP1 + ch * 64 + ko);
            }
            __syncthreads();
#pragma unroll
            for (int ks = 0; ks < 4; ks++) {
                uint32_t a[2][4], b[2][4];
#pragma unroll
                for (int mt = 0; mt < 2; mt++) {
                    uint32_t ad = sAu +
                        (uint32_t)((wm * 32 + mt * 16 + a_row) * (LDA * 2) +
                                   (ks * 16 + a_koff) * 2);
                    ldsm_x4(a[mt][0], a[mt][1], a[mt][2], a[mt][3], ad);
                }
#pragma unroll
                for (int np = 0; np < 2; np++) {
                    uint32_t bd = sBu +
                        (uint32_t)((wn * 32 + np * 16 + b_n) * (LDA * 2) +
                                   (ks * 16 + b_koff) * 2);
                    ldsm_x4(b[np][0], b[np][1], b[np][2], b[np][3], bd);
                }
#pragma unroll
                for (int mt = 0; mt < 2; mt++) {
#pragma unroll
                    for (int np = 0; np < 2; np++) {
                        uint32_t bfr0[2] = { b[np][0], b[np][2] };
                        uint32_t bfr1[2] = { b[np][1], b[np][3] };
                        mma_f16(acc[mt][2 * np + 0], a[mt], bfr0);
                        mma_f16(acc[mt][2 * np + 1], a[mt], bfr1);
                    }
                }
            }
        }
    }

    const int r_in = lane >> 2, c_in = (lane & 3) << 1;
#pragma unroll
    for (int mt = 0; mt < 2; mt++) {
        int rowbase = wm * 32 + mt * 16 + r_in;
#pragma unroll
        for (int nt = 0; nt < 4; nt++) {
            int col = wn * 32 + nt * 8 + c_in;
#pragma unroll
            for (int e = 0; e < 4; e++) {
                int rit = rowbase + ((e >> 1) << 3);
                int cc = col + (e & 1);
                float bb = (cc < 60) ? bias[cc] : 0.f;
                float v = gelu_f(acc[mt][nt][e] + bb);
                y1p[(size_t)(base + rit) * 64 + cc] = __float2half_rn(v);
            }
        }
    }
}

// ---------------- conv2: single-pass fp16 ----------------
__global__ void __launch_bounds__(256) conv2_tc(
    const __half* __restrict__ y1p, const __half* __restrict__ wh,
    const float* __restrict__ bias, float* __restrict__ y2) {
    __shared__ __align__(16) __half sA[128 * LDA];
    __shared__ __align__(16) __half sB[64 * LDA];
    const uint32_t sAu = smem_u32(sA), sBu = smem_u32(sB);
    const int tid = threadIdx.x, wid = tid >> 5, lane = tid & 31;
    const int wm = wid >> 1, wn = wid & 1;
    const int n0 = blockIdx.x * 64;
    const int tile = blockIdx.y;
    const int r = tile >> 1, c0 = (tile & 1) << 7;
    const int base = (r + 1) * PW + c0 + 1;
    const int a_row = lane & 15, a_koff = (lane >> 4) << 3;
    const int b_grp = lane >> 3, b_n = ((b_grp & 1) << 3) + (lane & 7), b_koff = (b_grp >> 1) << 3;
    float acc[2][4][4] = {};

    for (int tap = 0; tap < 9; tap++) {
        int dy = tap / 3 - 1, dx = tap % 3 - 1;
        int off = dy * PW + dx;
        __syncthreads();
#pragma unroll
        for (int it = 0; it < 4; it++) {
            int c = tid + it * 256;
            int rr = c >> 3, ko = (c & 7) << 3;
            *(uint4*)(sA + rr * LDA + ko) =
                *(const uint4*)(y1p + (size_t)(base + off + rr) * 64 + ko);
        }
#pragma unroll
        for (int it = 0; it < 2; it++) {
            int c = tid + it * 256;
            int rr = c >> 3, ko = (c & 7) << 3;
            *(uint4*)(sB + rr * LDA + ko) =
                *(const uint4*)(wh + (size_t)(tap * 192 + n0 + rr) * 64 + ko);
        }
        __syncthreads();
#pragma unroll
        for (int ks = 0; ks < 4; ks++) {
            uint32_t a[2][4], b[2][4];
#pragma unroll
            for (int mt = 0; mt < 2; mt++) {
                uint32_t ad = sAu +
                    (uint32_t)((wm * 32 + mt * 16 + a_row) * (LDA * 2) +
                               (ks * 16 + a_koff) * 2);
                ldsm_x4(a[mt][0], a[mt][1], a[mt][2], a[mt][3], ad);
            }
#pragma unroll
            for (int np = 0; np < 2; np++) {
                uint32_t bd = sBu +
                    (uint32_t)((wn * 32 + np * 16 + b_n) * (LDA * 2) +
                               (ks * 16 + b_koff) * 2);
                ldsm_x4(b[np][0], b[np][1], b[np][2], b[np][3], bd);
            }
#pragma unroll
            for (int mt = 0; mt < 2; mt++) {
#pragma unroll
                for (int np = 0; np < 2; np++) {
                    uint32_t bfr0[2] = { b[np][0], b[np][2] };
                    uint32_t bfr1[2] = { b[np][1], b[np][3] };
                    mma_f16(acc[mt][2 * np + 0], a[mt], bfr0);
                    mma_f16(acc[mt][2 * np + 1], a[mt], bfr1);
                }
            }
        }
    }

    const int r_in = lane >> 2, c_in = (lane & 3) << 1;
#pragma unroll
    for (int mt = 0; mt < 2; mt++) {
        int rowbase = wm * 32 + mt * 16 + r_in;
#pragma unroll
        for (int nt = 0; nt < 4; nt++) {
            int col = n0 + wn * 32 + nt * 8 + c_in;
#pragma unroll
            for (int e = 0; e < 4; e++) {
                int rit = rowbase + ((e >> 1) << 3);
                int cc = col + (e & 1);
                if (cc < CDIM) {
                    int p = r * 256 + c0 + rit;
                    y2[(size_t)p * CDIM + cc] = acc[mt][nt][e] + bias[cc];
                }
            }
        }
    }
}

// ---------------- LayerNorm fused with roll+window gather ----------------
__global__ void ln_kernel(const float* __restrict__ x, const float* __restrict__ g,
                          const float* __restrict__ b,
                          __half* __restrict__ ah, __half* __restrict__ al,
                          __half* __restrict__ xnp) {
    int p = blockIdx.x * 8 + (threadIdx.x >> 5);
    int lane = threadIdx.x & 31;
    const float* xr = x + (size_t)p * CDIM;
    float v[6];
    float s = 0.f;
#pragma unroll
    for (int k = 0; k < 6; k++) {
        int c = k * 32 + lane;
        v[k] = (c < CDIM) ? xr[c] : 0.f;
        s += v[k];
    }
    s = warp_sum(s);
    float mu = s * (1.0f / CDIM);
    float sq = 0.f;
#pragma unroll
    for (int k = 0; k < 6; k++) {
        int c = k * 32 + lane;
        if (c < CDIM) { float d = v[k] - mu; sq += d * d; }
    }
    sq = warp_sum(sq);
    float rstd = rsqrtf(sq * (1.0f / CDIM) + 1e-5f);
    int rr = p >> 8, cc = p & 255;
    int hs = (rr + 248) & 255, ws = (cc + 248) & 255;
    int widx = (((hs >> 4) << 4) + (ws >> 4)) * 256 + ((hs & 15) << 4) + (ws & 15);
    size_t aidx = (size_t)widx * KP1;
    size_t pidx = (size_t)((rr + 1) * PW + cc + 1) * KP1;
#pragma unroll
    for (int k = 0; k < 6; k++) {
        int c = k * 32 + lane;
        if (c < CDIM) {
            float y = (v[k] - mu) * rstd * g[c] + b[c];
            store_hilo(ah, al, aidx + c, y);
            xnp[pidx + c] = __float2half_rn(y);
        }
    }
}

// ---------------- channel attention pooling ----------------
__global__ void pool_kernel(const float* __restrict__ y2, float* __restrict__ casum) {
    int c = threadIdx.x;
    if (c >= CDIM) return;
    int p0 = blockIdx.x * 256;
    float s = 0.f;
    for (int i = 0; i < 256; i++) s += y2[(size_t)(p0 + i) * CDIM + c];
    atomicAdd(&casum[c], s);
}

__global__ void ca_kernel(const float* __restrict__ casum,
                          const float* __restrict__ w1, const float* __restrict__ b1,
                          const float* __restrict__ w2, const float* __restrict__ b2,
                          float* __restrict__ ca) {
    __shared__ float mean[CDIM];
    __shared__ float sq[6];
    int t = threadIdx.x;
    if (t < CDIM) mean[t] = casum[t] * (1.0f / NP);
    __syncthreads();
    if (t < 6) {
        float a = b1[t];
        for (int c = 0; c < CDIM; c++) a += mean[c] * w1[t * CDIM + c];
        sq[t] = fmaxf(a, 0.f);
    }
    __syncthreads();
    if (t < CDIM) {
        float a = b2[t];
#pragma unroll
        for (int s = 0; s < 6; s++) a += sq[s] * w2[t * 6 + s];
        ca[t] = 1.0f / (1.0f + __expf(-a));
    }
}

// ---------------- flash attention via mma.sync (block = window x head) ----------------
#define AQ_H 0
#define AQ_L 10240
#define AK_H 20480
#define AV_H 23040
#define ATTN_SMEM ((23040 + 32 * 72) * 2)

__global__ void __launch_bounds__(256, 1) attn_mma(
    const float* __restrict__ qkv,
    const __half* __restrict__ rpbb, const float* __restrict__ mask,
    __half* __restrict__ oh, __half* __restrict__ ol) {
    extern __shared__ __align__(16) __half smA[];
    const uint32_t smb = smem_u32(smA);
    const int win = blockIdx.x, head = blockIdx.y;
    const int tid = threadIdx.x, w = tid >> 5, lane = tid & 31;
    const int r_in = lane >> 2;
    const int a_row = lane & 15, a_koff = (lane >> 4) << 3;
    const int b_grp = lane >> 3, b_n = ((b_grp & 1) << 3) + (lane & 7), b_koff = (b_grp >> 1) << 3;
    const bool has_mask = ((win >> 4) == 15) || ((win & 15) == 15);

    {
        const float* qp = qkv + ((size_t)(win * 256 + tid)) * 540 + head * HD;
        __half* qh = smA + AQ_H + tid * 40;
        __half* ql = smA + AQ_L + tid * 40;
#pragma unroll
        for (int d = 0; d < 32; d++) {
            float v = (d < HD) ? qp[d] * 0.18257418583505536f : 0.f;
            __half h = __float2half_rn(v);
            qh[d] = h;
            ql[d] = __float2half_rn(v - __half2float(h));
        }
    }

    float accO[2][4][4] = {};
    float mrow[4] = { -1e30f, -1e30f, -1e30f, -1e30f };
    float lrow[4] = { 0.f, 0.f, 0.f, 0.f };

    const __half* rbbase = rpbb + (size_t)head * 65536;
    const float* mkbase = mask + (size_t)win * 65536;

    for (int chunk = 0; chunk < 4; chunk++) {
        const int kb = chunk * 64;
        __syncthreads();
        {
            int key = tid >> 2, dg = (tid & 3) * 8;
            const float* kp = qkv + ((size_t)(win * 256 + kb + key)) * 540 + 180 + head * HD;
            __half* kh = smA + AK_H + key * 40;
#pragma unroll
            for (int i = 0; i < 8; i++) {
                int d = dg + i;
                kh[d] = __float2half_rn((d < HD) ? kp[d] : 0.f);
            }
        }
        {
            int kp2 = (tid & 31) * 2;
            int d0 = tid >> 5;
            const float* vp0 = qkv + ((size_t)(win * 256 + kb + kp2)) * 540 + 360 + head * HD;
            const float* vp1 = vp0 + 540;
#pragma unroll
            for (int it = 0; it < 4; it++) {
                int d = d0 + it * 8;
                smA[AV_H + d * 72 + kp2] = __float2half_rn((d < HD) ? vp0[d] : 0.f);
                smA[AV_H + d * 72 + kp2 + 1] = __float2half_rn((d < HD) ? vp1[d] : 0.f);
            }
        }
        __syncthreads();

        // S = Q K^T, fused hi/lo: K frags loaded once per kk
        float accS[2][8][4] = {};
#pragma unroll
        for (int kk = 0; kk < 2; kk++) {
            uint32_t ah[2][4], al[2][4], b[4][4];
#pragma unroll
            for (int mt = 0; mt < 2; mt++) {
                uint32_t off = (uint32_t)((w * 32 + mt * 16 + a_row) * 80 +
                                          (kk * 16 + a_koff) * 2);
                ldsm_x4(ah[mt][0], ah[mt][1], ah[mt][2], ah[mt][3], smb + AQ_H * 2 + off);
                ldsm_x4(al[mt][0], al[mt][1], al[mt][2], al[mt][3], smb + AQ_L * 2 + off);
            }
#pragma unroll
            for (int np = 0; np < 4; np++) {
                uint32_t bd = smb + AK_H * 2 + (uint32_t)((np * 16 + b_n) * 80 +
                                                          (kk * 16 + b_koff) * 2);
                ldsm_x4(b[np][0], b[np][1], b[np][2], b[np][3], bd);
            }
#pragma unroll
            for (int mt = 0; mt < 2; mt++) {
#pragma unroll
                for (int np = 0; np < 4; np++) {
                    uint32_t f0[2] = { b[np][0], b[np][2] };
                    uint32_t f1[2] = { b[np][1], b[np][3] };
                    mma_f16(accS[mt][2 * np + 0], ah[mt], f0);
                    mma_f16(accS[mt][2 * np + 1], ah[mt], f1);
                    mma_f16(accS[mt][2 * np + 0], al[mt], f0);
                    mma_f16(accS[mt][2 * np + 1], al[mt], f1);
                }
            }
        }

#pragma unroll
        for (int mt = 0; mt < 2; mt++) {
            int r0 = w * 32 + mt * 16 + r_in;
            const __half* rb0 = rbbase + (size_t)r0 * 256;
            const __half* rb1 = rb0 + 8 * 256;
#pragma unroll
            for (int nt = 0; nt < 8; nt++) {
                int colb = kb + nt * 8 + ((lane & 3) << 1);
                float2 rA = __half22float2(*(const __half2*)(rb0 + colb));
                float2 rB = __half22float2(*(const __half2*)(rb1 + colb));
                accS[mt][nt][0] += rA.x;
                accS[mt][nt][1] += rA.y;
                accS[mt][nt][2] += rB.x;
                accS[mt][nt][3] += rB.y;
            }
            if (has_mask) {
                const float* mk0 = mkbase + (size_t)r0 * 256;
                const float* mk1 = mk0 + 8 * 256;
#pragma unroll
                for (int nt = 0; nt < 8; nt++) {
                    int colb = kb + nt * 8 + ((lane & 3) << 1);
                    float2 mA = *(const float2*)(mk0 + colb);
                    float2 mB = *(const float2*)(mk1 + colb);
                    accS[mt][nt][0] += mA.x;
                    accS[mt][nt][1] += mA.y;
                    accS[mt][nt][2] += mB.x;
                    accS[mt][nt][3] += mB.y;
                }
            }
        }

        float corr[4];
#pragma unroll
        for (int s2 = 0; s2 < 4; s2++) {
            int mt = s2 >> 1, h = s2 & 1;
            float mx = -1e30f;
#pragma unroll
            for (int nt = 0; nt < 8; nt++) {
                mx = fmaxf(mx, fmaxf(accS[mt][nt][h * 2], accS[mt][nt][h * 2 + 1]));
            }
            mx = fmaxf(mx, __shfl_xor_sync(0xffffffffu, mx, 1));
            mx = fmaxf(mx, __shfl_xor_sync(0xffffffffu, mx, 2));
            float mnew = fmaxf(mrow[s2], mx);
            corr[s2] = __expf(mrow[s2] - mnew);
            mrow[s2] = mnew;
            float rs = 0.f;
#pragma unroll
            for (int nt = 0; nt < 8; nt++) {
                float p0 = __expf(accS[mt][nt][h * 2] - mnew);
                float p1 = __expf(accS[mt][nt][h * 2 + 1] - mnew);
                accS[mt][nt][h * 2] = p0;
                accS[mt][nt][h * 2 + 1] = p1;
                rs += p0 + p1;
            }
            rs += __shfl_xor_sync(0xffffffffu, rs, 1);
            rs += __shfl_xor_sync(0xffffffffu, rs, 2);
            lrow[s2] = lrow[s2] * corr[s2] + rs;
        }
#pragma unroll
        for (int mt = 0; mt < 2; mt++)
#pragma unroll
            for (int nt = 0; nt < 4; nt++)
#pragma unroll
                for (int e = 0; e < 4; e++)
                    accO[mt][nt][e] *= corr[mt * 2 + (e >> 1)];

#pragma unroll
        for (int kk = 0; kk < 4; kk++) {
            uint32_t phi[2][4], plo[2][4];
#pragma unroll
            for (int mt = 0; mt < 2; mt++) {
                int nt0 = 2 * kk, nt1 = 2 * kk + 1;
                split2(accS[mt][nt0][0], accS[mt][nt0][1], phi[mt][0], plo[mt][0]);
                split2(accS[mt][nt0][2], accS[mt][nt0][3], phi[mt][1], plo[mt][1]);
                split2(accS[mt][nt1][0], accS[mt][nt1][1], phi[mt][2], plo[mt][2]);
                split2(accS[mt][nt1][2], accS[mt][nt1][3], phi[mt][3], plo[mt][3]);
            }
            uint32_t bh[2][4];
#pragma unroll
            for (int np = 0; np < 2; np++) {
                uint32_t adh = smb + AV_H * 2 +
                    (uint32_t)((np * 16 + b_n) * 144 + (kk * 16 + b_koff) * 2);
                ldsm_x4(bh[np][0], bh[np][1], bh[np][2], bh[np][3], adh);
            }
#pragma unroll
            for (int mt = 0; mt < 2; mt++) {
#pragma unroll
                for (int np = 0; np < 2; np++) {
                    uint32_t h0[2] = { bh[np][0], bh[np][2] };
                    uint32_t h1[2] = { bh[np][1], bh[np][3] };
                    mma_f16(accO[mt][2 * np + 0], phi[mt], h0);
                    mma_f16(accO[mt][2 * np + 1], phi[mt], h1);
                    mma_f16(accO[mt][2 * np + 0], plo[mt], h0);
                    mma_f16(accO[mt][2 * np + 1], plo[mt], h1);
                }
            }
        }
    }

    float inv[4];
#pragma unroll
    for (int s2 = 0; s2 < 4; s2++) inv[s2] = 1.0f / lrow[s2];
#pragma unroll
    for (int mt = 0; mt < 2; mt++) {
#pragma unroll
        for (int nt = 0; nt < 4; nt++) {
            int dbase = nt * 8 + ((lane & 3) << 1);
#pragma unroll
            for (int e = 0; e < 4; e++) {
                int d = dbase + (e & 1);
                if (d < HD) {
                    int row = w * 32 + mt * 16 + r_in + ((e >> 1) << 3);
                    float v = accO[mt][nt][e] * inv[mt * 2 + (e >> 1)];
                    store_hilo(oh, ol, (size_t)(win * 256 + row) * KP1 + head * HD + d, v);
                }
            }
        }
    }
}

// ---------------- residual combine + LN2 ----------------
__global__ void combine_ln2(const float* __restrict__ x, const float* __restrict__ proj,
                            const float* __restrict__ y2, const float* __restrict__ ca,
                            const float* __restrict__ g2, const float* __restrict__ b2,
                            float* __restrict__ x1,
                            __half* __restrict__ mh, __half* __restrict__ ml) {
    int p = blockIdx.x * 8 + (threadIdx.x >> 5);
    int lane = threadIdx.x & 31;
    int r = p >> 8, cc = p & 255;
    int hs = (r + 248) & 255;
    int ws2 = (cc + 248) & 255;
    int widx = (((hs >> 4) << 4) + (ws2 >> 4)) * 256 + ((hs & 15) << 4) + (ws2 & 15);
    float v[6];
    float s = 0.f;
#pragma unroll
    for (int k = 0; k < 6; k++) {
        int c = k * 32 + lane;
        if (c < CDIM) {
            v[k] = x[(size_t)p * CDIM + c] + proj[(size_t)widx * CDIM + c]
                 + 0.01f * y2[(size_t)p * CDIM + c] * ca[c];
        } else v[k] = 0.f;
        s += v[k];
    }
    s = warp_sum(s);
    float mu = s * (1.0f / CDIM);
    float sq = 0.f;
#pragma unroll
    for (int k = 0; k < 6; k++) {
        int c = k * 32 + lane;
        if (c < CDIM) { float d = v[k] - mu; sq += d * d; }
    }
    sq = warp_sum(sq);
    float rstd = rsqrtf(sq * (1.0f / CDIM) + 1e-5f);
#pragma unroll
    for (int k = 0; k < 6; k++) {
        int c = k * 32 + lane;
        if (c < CDIM) {
            x1[(size_t)p * CDIM + c] = v[k];
            store_hilo(mh, ml, (size_t)p * KP1 + c, (v[k] - mu) * rstd * g2[c] + b2[c]);
        }
    }
}

// ---------------- launcher ----------------
extern "C" void kernel_launch(void* const* d_in, const int* in_sizes, int n_in,
                              void* d_out, int out_size) {
    const float* x     = (const float*)d_in[0];
    const int*   rpi   = (const int*)d_in[3];
    const float* mask  = (const float*)d_in[4];
    const float* n1g   = (const float*)d_in[5];
    const float* n1b   = (const float*)d_in[6];
    const float* qkvw  = (const float*)d_in[7];
    const float* qkvb  = (const float*)d_in[8];
    const float* rpbt  = (const float*)d_in[9];
    const float* projw = (const float*)d_in[10];
    const float* projb = (const float*)d_in[11];
    const float* c1w   = (const float*)d_in[12];
    const float* c1b   = (const float*)d_in[13];
    const float* c2w   = (const float*)d_in[14];
    const float* c2b   = (const float*)d_in[15];
    const float* ca1w  = (const float*)d_in[16];
    const float* ca1b  = (const float*)d_in[17];
    const float* ca2w  = (const float*)d_in[18];
    const float* ca2b  = (const float*)d_in[19];
    const float* n2g   = (const float*)d_in[20];
    const float* n2b   = (const float*)d_in[21];
    const float* f1w   = (const float*)d_in[22];
    const float* f1b   = (const float*)d_in[23];
    const float* f2w   = (const float*)d_in[24];
    const float* f2b   = (const float*)d_in[25];
    float* out = (float*)d_out;

    float *qkv, *proj, *y2, *casum, *ca, *x1;
    __half *rpbb, *xnp, *y1p, *ahi, *alo, *mhi, *mlo;
    __half *bqh, *bph, *b1h, *b2h, *wc1h, *wc2h;
    cudaGetSymbolAddress((void**)&qkv, g_qkv);
    cudaGetSymbolAddress((void**)&proj, g_proj);
    cudaGetSymbolAddress((void**)&y2, g_y2);
    cudaGetSymbolAddress((void**)&rpbb, g_rpbb);
    cudaGetSymbolAddress((void**)&casum, g_casum);
    cudaGetSymbolAddress((void**)&ca, g_ca);
    cudaGetSymbolAddress((void**)&x1, g_x1);
    cudaGetSymbolAddress((void**)&xnp, g_xnp);
    cudaGetSymbolAddress((void**)&y1p, g_y1p);
    cudaGetSymbolAddress((void**)&ahi, g_ahi);
    cudaGetSymbolAddress((void**)&alo, g_alo);
    cudaGetSymbolAddress((void**)&mhi, g_mhi);
    cudaGetSymbolAddress((void**)&mlo, g_mlo);
    cudaGetSymbolAddress((void**)&bqh, g_bqh);
    cudaGetSymbolAddress((void**)&bph, g_bph);
    cudaGetSymbolAddress((void**)&b1h, g_b1h);
    cudaGetSymbolAddress((void**)&b2h, g_b2h);
    cudaGetSymbolAddress((void**)&wc1h, g_wc1h);
    cudaGetSymbolAddress((void**)&wc2h, g_wc2h);

    cudaFuncSetAttribute(tc_gemm2<0>, cudaFuncAttributeMaxDynamicSharedMemorySize, G2_SMEM);
    cudaFuncSetAttribute(tc_gemm2<1>, cudaFuncAttributeMaxDynamicSharedMemorySize, G2_SMEM);
    cudaFuncSetAttribute(tc_mlp2, cudaFuncAttributeMaxDynamicSharedMemorySize, MLP_SMEM);
    cudaFuncSetAttribute(attn_mma, cudaFuncAttributeMaxDynamicSharedMemorySize, ATTN_SMEM);

    // single merged prep (weights, rpb, casum zero)
    mega_prep<<<2849, 256>>>(qkvw, projw, f1w, f2w, c1w, c2w, rpi, rpbt,
                             bqh, bph, b1h, b2h, wc1h, wc2h, rpbb, casum);
    ln_kernel<<<NP / 8, 256>>>(x, n1g, n1b, ahi, alo, xnp);

    // fork: conv branch on s2 (depends on ln output + mega_prep, both on legacy)
    cudaEventRecord(g_aux.ev0, 0);
    cudaStreamWaitEvent(g_aux.s2, g_aux.ev0, 0);
    conv1_tc<<<512, 256, 0, g_aux.s2>>>(xnp, wc1h, c1b, y1p);
    conv2_tc<<<dim3(3, 512), 256, 0, g_aux.s2>>>(y1p, wc2h, c2b, y2);
    pool_kernel<<<256, 192, 0, g_aux.s2>>>(y2, casum);
    ca_kernel<<<1, 192, 0, g_aux.s2>>>(casum, ca1w, ca1b, ca2w, ca2b, ca);
    cudaEventRecord(g_aux.ev1, g_aux.s2);

    // attention chain on legacy stream (concurrent with conv branch)
    tc_gemm2<0><<<512, 256, G2_SMEM>>>(ahi, alo, bqh, qkvb, qkv,
                                       nullptr, nullptr, 540, 540, 9);
    attn_mma<<<dim3(256, 6), 256, ATTN_SMEM>>>(qkv, rpbb, mask, ahi, alo);
    tc_gemm2<0><<<512, 256, G2_SMEM>>>(ahi, alo, bph, projb, proj,
                                       nullptr, nullptr, 180, 180, 3);

    // join conv branch, then combine + MLP
    cudaStreamWaitEvent(0, g_aux.ev1, 0);
    combine_ln2<<<NP / 8, 256>>>(x, proj, y2, ca, n2g, n2b, x1, ahi, alo);
    tc_gemm2<1><<<512, 256, G2_SMEM>>>(ahi, alo, b1h, f1b, nullptr, mhi, mlo,
                                       720, 768, 12);
    tc_mlp2<<<512, 256, MLP_SMEM>>>(mhi, mlo, b2h, f2b, x1, out);
}

// round 17
// speedup vs baseline: 1.0266x; 1.0266x over previous
#include <cuda_runtime.h>
#include <cuda_fp16.h>
#include <math.h>
#include <stdint.h>

#define NP 65536
#define CDIM 180
#define NHEADS 6
#define HD 30
#define HID 720
#define KP1 192
#define KP2 768
#define PW 258   // padded image width/height

// ---------------- scratch (device globals; no allocations) ----------------
__device__ __align__(16) float g_qkv[NP * 540];
__device__ __align__(16) float g_proj[NP * CDIM];
__device__ __align__(16) float g_y2[NP * CDIM];
__device__ __align__(16) __half g_rpbb[NHEADS * 65536];
__device__ float g_casum[CDIM];
__device__ float g_ca[CDIM];
__device__ __align__(16) float g_x1[NP * CDIM];
// padded fp16 image for conv branch (halo stays zero forever)
__device__ __align__(16) __half g_xnp[PW * PW * KP1];
__device__ __align__(16) __half g_y1p[PW * PW * 64];
// fp16 split activations (zero-initialized; K-pad columns stay zero forever)
__device__ __align__(16) __half g_ahi[NP * KP1];
__device__ __align__(16) __half g_alo[NP * KP1];
__device__ __align__(16) __half g_mhi[NP * KP2];
__device__ __align__(16) __half g_mlo[NP * KP2];
// fp16 transposed weights [N_pad][K_pad]
__device__ __align__(16) __half g_bqh[576 * KP1];
__device__ __align__(16) __half g_bph[192 * KP1];
__device__ __align__(16) __half g_b1h[768 * KP1];
__device__ __align__(16) __half g_b2h[192 * KP2];
// conv weights: [tap][ocpad][kpad] fp16
__device__ __align__(16) __half g_wc1h[9 * 64 * KP1];
__device__ __align__(16) __half g_wc2h[9 * 192 * 64];

// streams/events created pre-main (static init) so no allocations inside kernel_launch
namespace {
struct Aux {
    cudaStream_t s2;
    cudaEvent_t ev0, ev1;
    Aux() {
        cudaStreamCreateWithFlags(&s2, cudaStreamNonBlocking);
        cudaEventCreateWithFlags(&ev0, cudaEventDisableTiming);
        cudaEventCreateWithFlags(&ev1, cudaEventDisableTiming);
    }
};
Aux g_aux;
}

__device__ __forceinline__ float gelu_f(float x) {
    return 0.5f * x * (1.0f + erff(x * 0.70710678118654752f));
}
__device__ __forceinline__ float warp_sum(float v) {
    for (int o = 16; o > 0; o >>= 1) v += __shfl_xor_sync(0xffffffffu, v, o);
    return v;
}
__device__ __forceinline__ void store_hilo(__half* h, __half* l, size_t idx, float v) {
    __half hh = __float2half_rn(v);
    h[idx] = hh;
    l[idx] = __float2half_rn(v - __half2float(hh));
}
__device__ __forceinline__ uint32_t smem_u32(const void* p) {
    uint32_t a;
    asm("{ .reg .u64 t; cvta.to.shared.u64 t, %1; cvt.u32.u64 %0, t; }" : "=r"(a) : "l"(p));
    return a;
}
__device__ __forceinline__ void ldsm_x4(uint32_t& r0, uint32_t& r1, uint32_t& r2, uint32_t& r3,
                                        uint32_t addr) {
    asm volatile("ldmatrix.sync.aligned.m8n8.x4.shared.b16 {%0,%1,%2,%3}, [%4];"
                 : "=r"(r0), "=r"(r1), "=r"(r2), "=r"(r3) : "r"(addr));
}
__device__ __forceinline__ void mma_f16(float* c, const uint32_t* a, const uint32_t* b) {
    asm volatile(
        "mma.sync.aligned.m16n8k16.row.col.f32.f16.f16.f32 "
        "{%0,%1,%2,%3}, {%4,%5,%6,%7}, {%8,%9}, {%0,%1,%2,%3};"
        : "+f"(c[0]), "+f"(c[1]), "+f"(c[2]), "+f"(c[3])
        : "r"(a[0]), "r"(a[1]), "r"(a[2]), "r"(a[3]), "r"(b[0]), "r"(b[1]));
}
__device__ __forceinline__ void split2(float a, float b, uint32_t& hi, uint32_t& lo) {
    __half ah = __float2half_rn(a), bh = __float2half_rn(b);
    __half2 h2; h2.x = ah; h2.y = bh;
    hi = *(uint32_t*)&h2;
    __half2 l2;
    l2.x = __float2half_rn(a - __half2float(ah));
    l2.y = __float2half_rn(b - __half2float(bh));
    lo = *(uint32_t*)&l2;
}
__device__ __forceinline__ void cp16(uint32_t s, const void* g) {
    asm volatile("cp.async.cg.shared.global [%0], [%1], 16;" :: "r"(s), "l"(g));
}
#define CP_COMMIT asm volatile("cp.async.commit_group;")
#define CP_WAIT0 asm volatile("cp.async.wait_group 0;" ::: "memory")

// ---------------- merged weight prep + rpb + casum zero (one launch) ----------------
__global__ void mega_prep(const float* __restrict__ qkvw, const float* __restrict__ projw,
                          const float* __restrict__ f1w, const float* __restrict__ f2w,
                          const float* __restrict__ c1w, const float* __restrict__ c2w,
                          const int* __restrict__ rpi, const float* __restrict__ rpbt,
                          __half* __restrict__ bqh, __half* __restrict__ bph,
                          __half* __restrict__ b1h, __half* __restrict__ b2h,
                          __half* __restrict__ wc1h, __half* __restrict__ wc2h,
                          __half* __restrict__ rpbb, float* __restrict__ casum) {
    int b = blockIdx.x, t = threadIdx.x;
    if (b < 432) {
        int idx = b * 256 + t;
        if (idx < 576 * 192) {
            int n = idx / 192, k = idx % 192;
            bqh[idx] = __float2half_rn((n < 540 && k < 180) ? qkvw[k * 540 + n] : 0.f);
        }
    } else if (b < 576) {
        int idx = (b - 432) * 256 + t;
        if (idx < 192 * 192) {
            int n = idx / 192, k = idx % 192;
            bph[idx] = __float2half_rn((n < 180 && k < 180) ? projw[k * 180 + n] : 0.f);
        }
    } else if (b < 1152) {
        int idx = (b - 576) * 256 + t;
        if (idx < 768 * 192) {
            int n = idx / 192, k = idx % 192;
            b1h[idx] = __float2half_rn((n < 720 && k < 180) ? f1w[k * 720 + n] : 0.f);
        }
    } else if (b < 1728) {
        int idx = (b - 1152) * 256 + t;
        if (idx < 192 * 768) {
            int n = idx / 768, k = idx % 768;
            b2h[idx] = __float2half_rn((n < 180 && k < 720) ? f2w[k * 180 + n] : 0.f);
        }
    } else if (b < 2160) {
        int idx = (b - 1728) * 256 + t;
        if (idx < 9 * 64 * KP1) {
            int k = idx % KP1;
            int rest = idx / KP1;
            int oc = rest % 64, tap = rest / 64;
            wc1h[idx] = __float2half_rn((oc < 60 && k < 180) ? c1w[(oc * 180 + k) * 9 + tap] : 0.f);
        }
    } else if (b < 2592) {
        int idx = (b - 2160) * 256 + t;
        if (idx < 9 * 192 * 64) {
            int k = idx % 64;
            int rest = idx / 64;
            int oc = rest % 192, tap = rest / 192;
            wc2h[idx] = __float2half_rn((oc < 180 && k < 60) ? c2w[(oc * 60 + k) * 9 + tap] : 0.f);
        }
    } else if (b < 2848) {
        int idx = (b - 2592) * 256 + t;
        int r = rpi[idx];
#pragma unroll
        for (int h = 0; h < NHEADS; h++)
            rpbb[h * 65536 + idx] = __float2half_rn(rpbt[r * NHEADS + h]);
    } else {
        if (t < CDIM) casum[t] = 0.f;
    }
}

// ---------------- persistent-A GEMM (Kpad=192), 2-pass fp16, pipelined B ----------------
#define LDA2 200
#define G2_A_ELEMS (128 * LDA2)
#define G2_B_ELEMS (64 * LDA2)
#define G2_SMEM ((2 * G2_A_ELEMS + 2 * G2_B_ELEMS) * 2)

template <int EPI>
__global__ void __launch_bounds__(256) tc_gemm2(
    const __half* __restrict__ Ahi, const __half* __restrict__ Alo,
    const __half* __restrict__ Bh,
    const float* __restrict__ bias,
    float* __restrict__ Cf, __half* __restrict__ Chi, __half* __restrict__ Clo,
    int Nvalid, int ldc, int ntiles) {
    extern __shared__ __align__(16) char sm2[];
    __half* sAh = (__half*)sm2;
    __half* sAl = sAh + G2_A_ELEMS;
    __half* sB = sAl + G2_A_ELEMS;
    const uint32_t sAhu = smem_u32(sAh), sAlu = smem_u32(sAl);
    const uint32_t sBu = smem_u32(sB);
    const int tid = threadIdx.x, wid = tid >> 5, lane = tid & 31;
    const int wm = wid >> 1, wn = wid & 1;
    const int m0 = blockIdx.x * 128;
    const int a_row = lane & 15, a_koff = (lane >> 4) << 3;
    const int b_grp = lane >> 3, b_n = ((b_grp & 1) << 3) + (lane & 7), b_koff = (b_grp >> 1) << 3;
    const int r_in = lane >> 2, c_in = (lane & 3) << 1;

#pragma unroll
    for (int it = 0; it < 12; it++) {
        int c = tid + it * 256;
        int rr = c / 24, ko = (c % 24) * 8;
        size_t ga = (size_t)(m0 + rr) * KP1 + ko;
        cp16(sAhu + (rr * LDA2 + ko) * 2, Ahi + ga);
        cp16(sAlu + (rr * LDA2 + ko) * 2, Alo + ga);
    }
#pragma unroll
    for (int it = 0; it < 6; it++) {
        int c = tid + it * 256;
        int rr = c / 24, ko = (c % 24) * 8;
        cp16(sBu + (rr * LDA2 + ko) * 2, Bh + (size_t)rr * KP1 + ko);
    }
    CP_COMMIT;

    for (int nt = 0; nt < ntiles; nt++) {
        const int n0 = nt * 64;
        CP_WAIT0;
        __syncthreads();
        if (nt + 1 < ntiles) {
            const uint32_t dst = sBu + (((nt + 1) & 1) * G2_B_ELEMS) * 2;
            const int nn0 = (nt + 1) * 64;
#pragma unroll
            for (int it = 0; it < 6; it++) {
                int c = tid + it * 256;
                int rr = c / 24, ko = (c % 24) * 8;
                cp16(dst + (rr * LDA2 + ko) * 2, Bh + (size_t)(nn0 + rr) * KP1 + ko);
            }
            CP_COMMIT;
        }
        const uint32_t bufH = sBu + ((nt & 1) * G2_B_ELEMS) * 2;

        float acc[2][4][4] = {};
#pragma unroll
        for (int pass = 0; pass < 2; pass++) {
            const uint32_t aBase = pass ? sAlu : sAhu;
#pragma unroll
            for (int ks = 0; ks < 12; ks++) {
                uint32_t a[2][4], b[2][4];
#pragma unroll
                for (int mt = 0; mt < 2; mt++) {
                    uint32_t ad = aBase +
                        (uint32_t)((wm * 32 + mt * 16 + a_row) * (LDA2 * 2) +
                                   (ks * 16 + a_koff) * 2);
                    ldsm_x4(a[mt][0], a[mt][1], a[mt][2], a[mt][3], ad);
                }
#pragma unroll
                for (int np = 0; np < 2; np++) {
                    uint32_t bd = bufH +
                        (uint32_t)((wn * 32 + np * 16 + b_n) * (LDA2 * 2) +
                                   (ks * 16 + b_koff) * 2);
                    ldsm_x4(b[np][0], b[np][1], b[np][2], b[np][3], bd);
                }
#pragma unroll
                for (int mt = 0; mt < 2; mt++) {
#pragma unroll
                    for (int np = 0; np < 2; np++) {
                        uint32_t bfr0[2] = { b[np][0], b[np][2] };
                        uint32_t bfr1[2] = { b[np][1], b[np][3] };
                        mma_f16(acc[mt][2 * np + 0], a[mt], bfr0);
                        mma_f16(acc[mt][2 * np + 1], a[mt], bfr1);
                    }
                }
            }
        }
#pragma unroll
        for (int mt = 0; mt < 2; mt++) {
            int mrow = m0 + wm * 32 + mt * 16 + r_in;
#pragma unroll
            for (int ntb = 0; ntb < 4; ntb++) {
                int col = n0 + wn * 32 + ntb * 8 + c_in;
#pragma unroll
                for (int e = 0; e < 4; e++) {
                    int rr = mrow + ((e >> 1) << 3);
                    int cc = col + (e & 1);
                    if (cc < Nvalid) {
                        float v = acc[mt][ntb][e] + bias[cc];
                        if (EPI == 0) {
                            Cf[(size_t)rr * ldc + cc] = v;
                        } else {
                            store_hilo(Chi, Clo, (size_t)rr * ldc + cc, gelu_f(v));
                        }
                    }
                }
            }
        }
    }
}

// ---------------- fc2: persistent accumulators over all 3 n-tiles, 2-pass fp16 ----------------
#define MLDA 72
#define MLP_A_ELEMS (128 * MLDA)
#define MLP_B_ELEMS (192 * MLDA)
#define MLP_BUF (2 * MLP_A_ELEMS + MLP_B_ELEMS)
#define MLP_SMEM (2 * MLP_BUF * 2)

__global__ void __launch_bounds__(256, 1) tc_mlp2(
    const __half* __restrict__ Ahi, const __half* __restrict__ Alo,
    const __half* __restrict__ Bh,
    const float* __restrict__ bias, const float* __restrict__ res,
    float* __restrict__ Cf) {
    extern __shared__ __align__(16) char smm[];
    const uint32_t smu = smem_u32(smm);
    const int tid = threadIdx.x, wid = tid >> 5, lane = tid & 31;
    const int wm = wid >> 1, wn = wid & 1;
    const int m0 = blockIdx.x * 128;
    const int a_row = lane & 15, a_koff = (lane >> 4) << 3;
    const int b_grp = lane >> 3, b_n = ((b_grp & 1) << 3) + (lane & 7), b_koff = (b_grp >> 1) << 3;
    const int r_in = lane >> 2, c_in = (lane & 3) << 1;

    {
        const uint32_t aH = smu, aL = smu + MLP_A_ELEMS * 2;
        const uint32_t bH = smu + 2 * MLP_A_ELEMS * 2;
#pragma unroll
        for (int it = 0; it < 4; it++) {
            int c = tid + it * 256;
            int rr = c >> 3, ko = (c & 7) * 8;
            size_t ga = (size_t)(m0 + rr) * KP2 + ko;
            cp16(aH + (rr * MLDA + ko) * 2, Ahi + ga);
            cp16(aL + (rr * MLDA + ko) * 2, Alo + ga);
        }
#pragma unroll
        for (int it = 0; it < 6; it++) {
            int c = tid + it * 256;
            int rr = c >> 3, ko = (c & 7) * 8;
            cp16(bH + (rr * MLDA + ko) * 2, Bh + (size_t)rr * KP2 + ko);
        }
        CP_COMMIT;
    }

    float acc[3][2][4][4] = {};

    for (int kc = 0; kc < 12; kc++) {
        CP_WAIT0;
        __syncthreads();
        if (kc + 1 < 12) {
            const uint32_t base = smu + (((kc + 1) & 1) * MLP_BUF) * 2;
            const uint32_t aH = base, aL = base + MLP_A_ELEMS * 2;
            const uint32_t bH = base + 2 * MLP_A_ELEMS * 2;
            const int k0 = (kc + 1) * 64;
#pragma unroll
            for (int it = 0; it < 4; it++) {
                int c = tid + it * 256;
                int rr = c >> 3, ko = (c & 7) * 8;
                size_t ga = (size_t)(m0 + rr) * KP2 + k0 + ko;
                cp16(aH + (rr * MLDA + ko) * 2, Ahi + ga);
                cp16(aL + (rr * MLDA + ko) * 2, Alo + ga);
            }
#pragma unroll
            for (int it = 0; it < 6; it++) {
                int c = tid + it * 256;
                int rr = c >> 3, ko = (c & 7) * 8;
                cp16(bH + (rr * MLDA + ko) * 2, Bh + (size_t)rr * KP2 + k0 + ko);
            }
            CP_COMMIT;
        }
        const uint32_t base = smu + ((kc & 1) * MLP_BUF) * 2;
        const uint32_t aH = base, aL = base + MLP_A_ELEMS * 2;
        const uint32_t bH = base + 2 * MLP_A_ELEMS * 2;

#pragma unroll
        for (int pass = 0; pass < 2; pass++) {
            const uint32_t aBase = pass ? aL : aH;
#pragma unroll
            for (int ks = 0; ks < 4; ks++) {
                uint32_t a[2][4];
#pragma unroll
                for (int mt = 0; mt < 2; mt++) {
                    uint32_t ad = aBase +
                        (uint32_t)((wm * 32 + mt * 16 + a_row) * (MLDA * 2) +
                                   (ks * 16 + a_koff) * 2);
                    ldsm_x4(a[mt][0], a[mt][1], a[mt][2], a[mt][3], ad);
                }
#pragma unroll
                for (int t = 0; t < 3; t++) {
                    uint32_t b[2][4];
#pragma unroll
                    for (int np = 0; np < 2; np++) {
                        uint32_t bd = bH +
                            (uint32_t)((t * 64 + wn * 32 + np * 16 + b_n) * (MLDA * 2) +
                                       (ks * 16 + b_koff) * 2);
                        ldsm_x4(b[np][0], b[np][1], b[np][2], b[np][3], bd);
                    }
#pragma unroll
                    for (int mt = 0; mt < 2; mt++) {
#pragma unroll
                        for (int np = 0; np < 2; np++) {
                            uint32_t f0[2] = { b[np][0], b[np][2] };
                            uint32_t f1[2] = { b[np][1], b[np][3] };
                            mma_f16(acc[t][mt][2 * np + 0], a[mt], f0);
                            mma_f16(acc[t][mt][2 * np + 1], a[mt], f1);
                        }
                    }
                }
            }
        }
    }

#pragma unroll
    for (int t = 0; t < 3; t++) {
#pragma unroll
        for (int mt = 0; mt < 2; mt++) {
            int mrow = m0 + wm * 32 + mt * 16 + r_in;
#pragma unroll
            for (int nt = 0; nt < 4; nt++) {
                int col = t * 64 + wn * 32 + nt * 8 + c_in;
#pragma unroll
                for (int e = 0; e < 4; e++) {
                    int rr = mrow + ((e >> 1) << 3);
                    int cc = col + (e & 1);
                    if (cc < CDIM) {
                        Cf[(size_t)rr * CDIM + cc] =
                            acc[t][mt][nt][e] + bias[cc] + res[(size_t)rr * CDIM + cc];
                    }
                }
            }
        }
    }
}

// ---------------- conv1: dy-row halo staging (27 -> 9 stages), fp16 ----------------
#define CLDA 72
__global__ void __launch_bounds__(256) conv1_tc(
    const __half* __restrict__ xnp, const __half* __restrict__ wh,
    const float* __restrict__ bias, __half* __restrict__ y1p) {
    __shared__ __align__(16) __half sA[130 * CLDA];   // 130 px halo x 64 ch
    __shared__ __align__(16) __half sB[192 * CLDA];   // 3 dx taps x 64 oc
    const uint32_t sAu = smem_u32(sA), sBu = smem_u32(sB);
    const int tid = threadIdx.x, wid = tid >> 5, lane = tid & 31;
    const int wm = wid >> 1, wn = wid & 1;
    const int tile = blockIdx.x;
    const int r = tile >> 1, c0 = (tile & 1) << 7;
    const int a_row = lane & 15, a_koff = (lane >> 4) << 3;
    const int b_grp = lane >> 3, b_n = ((b_grp & 1) << 3) + (lane & 7), b_koff = (b_grp >> 1) << 3;
    float acc[2][4][4] = {};

    for (int ch = 0; ch < 3; ch++) {
        for (int dy = 0; dy < 3; dy++) {
            __syncthreads();
            // stage A halo: 130 px row (r+dy), this 64-ch chunk
            for (int idx = tid; idx < 1040; idx += 256) {
                int row = idx >> 3, ko = (idx & 7) << 3;
                *(uint4*)(sA + row * CLDA + ko) =
                    *(const uint4*)(xnp + (size_t)((r + dy) * PW + c0 + row) * KP1 + ch * 64 + ko);
            }
            // stage B: 3 dx taps x 64 oc for this ch chunk
            for (int idx = tid; idx < 1536; idx += 256) {
                int row = idx >> 3, ko = (idx & 7) << 3;
                int dx = row >> 6, oc = row & 63;
                *(uint4*)(sB + row * CLDA + ko) =
                    *(const uint4*)(wh + (size_t)((dy * 3 + dx) * 64 + oc) * KP1 + ch * 64 + ko);
            }
            __syncthreads();
#pragma unroll
            for (int dx = 0; dx < 3; dx++) {
#pragma unroll
                for (int ks = 0; ks < 4; ks++) {
                    uint32_t a[2][4], b[2][4];
#pragma unroll
                    for (int mt = 0; mt < 2; mt++) {
                        uint32_t ad = sAu +
                            (uint32_t)((dx + wm * 32 + mt * 16 + a_row) * (CLDA * 2) +
                                       (ks * 16 + a_koff) * 2);
                        ldsm_x4(a[mt][0], a[mt][1], a[mt][2], a[mt][3], ad);
                    }
#pragma unroll
                    for (int np = 0; np < 2; np++) {
                        uint32_t bd = sBu +
                            (uint32_t)((dx * 64 + wn * 32 + np * 16 + b_n) * (CLDA * 2) +
                                       (ks * 16 + b_koff) * 2);
                        ldsm_x4(b[np][0], b[np][1], b[np][2], b[np][3], bd);
                    }
#pragma unroll
                    for (int mt = 0; mt < 2; mt++) {
#pragma unroll
                        for (int np = 0; np < 2; np++) {
                            uint32_t f0[2] = { b[np][0], b[np][2] };
                            uint32_t f1[2] = { b[np][1], b[np][3] };
                            mma_f16(acc[mt][2 * np + 0], a[mt], f0);
                            mma_f16(acc[mt][2 * np + 1], a[mt], f1);
                        }
                    }
                }
            }
        }
    }

    const int r_in = lane >> 2, c_in = (lane & 3) << 1;
    const int base = (r + 1) * PW + c0 + 1;
#pragma unroll
    for (int mt = 0; mt < 2; mt++) {
        int rowbase = wm * 32 + mt * 16 + r_in;
#pragma unroll
        for (int nt = 0; nt < 4; nt++) {
            int col = wn * 32 + nt * 8 + c_in;
#pragma unroll
            for (int e = 0; e < 4; e++) {
                int rit = rowbase + ((e >> 1) << 3);
                int cc = col + (e & 1);
                float bb = (cc < 60) ? bias[cc] : 0.f;
                float v = gelu_f(acc[mt][nt][e] + bb);
                y1p[(size_t)(base + rit) * 64 + cc] = __float2half_rn(v);
            }
        }
    }
}

// ---------------- conv2: dy-row halo staging (9 -> 3 stages), fp16 ----------------
__global__ void __launch_bounds__(256) conv2_tc(
    const __half* __restrict__ y1p, const __half* __restrict__ wh,
    const float* __restrict__ bias, float* __restrict__ y2) {
    __shared__ __align__(16) __half sA[130 * CLDA];
    __shared__ __align__(16) __half sB[192 * CLDA];
    const uint32_t sAu = smem_u32(sA), sBu = smem_u32(sB);
    const int tid = threadIdx.x, wid = tid >> 5, lane = tid & 31;
    const int wm = wid >> 1, wn = wid & 1;
    const int n0 = blockIdx.x * 64;
    const int tile = blockIdx.y;
    const int r = tile >> 1, c0 = (tile & 1) << 7;
    const int a_row = lane & 15, a_koff = (lane >> 4) << 3;
    const int b_grp = lane >> 3, b_n = ((b_grp & 1) << 3) + (lane & 7), b_koff = (b_grp >> 1) << 3;
    float acc[2][4][4] = {};

    for (int dy = 0; dy < 3; dy++) {
        __syncthreads();
        // stage A halo: 130 px row (r+dy), 64 ch
        for (int idx = tid; idx < 1040; idx += 256) {
            int row = idx >> 3, ko = (idx & 7) << 3;
            *(uint4*)(sA + row * CLDA + ko) =
                *(const uint4*)(y1p + (size_t)((r + dy) * PW + c0 + row) * 64 + ko);
        }
        // stage B: 3 dx taps x 64 oc (this oc tile)
        for (int idx = tid; idx < 1536; idx += 256) {
            int row = idx >> 3, ko = (idx & 7) << 3;
            int dx = row >> 6, oc = row & 63;
            *(uint4*)(sB + row * CLDA + ko) =
                *(const uint4*)(wh + (size_t)((dy * 3 + dx) * 192 + n0 + oc) * 64 + ko);
        }
        __syncthreads();
#pragma unroll
        for (int dx = 0; dx < 3; dx++) {
#pragma unroll
            for (int ks = 0; ks < 4; ks++) {
                uint32_t a[2][4], b[2][4];
#pragma unroll
                for (int mt = 0; mt < 2; mt++) {
                    uint32_t ad = sAu +
                        (uint32_t)((dx + wm * 32 + mt * 16 + a_row) * (CLDA * 2) +
                                   (ks * 16 + a_koff) * 2);
                    ldsm_x4(a[mt][0], a[mt][1], a[mt][2], a[mt][3], ad);
                }
#pragma unroll
                for (int np = 0; np < 2; np++) {
                    uint32_t bd = sBu +
                        (uint32_t)((dx * 64 + wn * 32 + np * 16 + b_n) * (CLDA * 2) +
                                   (ks * 16 + b_koff) * 2);
                    ldsm_x4(b[np][0], b[np][1], b[np][2], b[np][3], bd);
                }
#pragma unroll
                for (int mt = 0; mt < 2; mt++) {
#pragma unroll
                    for (int np = 0; np < 2; np++) {
                        uint32_t f0[2] = { b[np][0], b[np][2] };
                        uint32_t f1[2] = { b[np][1], b[np][3] };
                        mma_f16(acc[mt][2 * np + 0], a[mt], f0);
                        mma_f16(acc[mt][2 * np + 1], a[mt], f1);
                    }
                }
            }
        }
    }

    const int r_in = lane >> 2, c_in = (lane & 3) << 1;
#pragma unroll
    for (int mt = 0; mt < 2; mt++) {
        int rowbase = wm * 32 + mt * 16 + r_in;
#pragma unroll
        for (int nt = 0; nt < 4; nt++) {
            int col = n0 + wn * 32 + nt * 8 + c_in;
#pragma unroll
            for (int e = 0; e < 4; e++) {
                int rit = rowbase + ((e >> 1) << 3);
                int cc = col + (e & 1);
                if (cc < CDIM) {
                    int p = r * 256 + c0 + rit;
                    y2[(size_t)p * CDIM + cc] = acc[mt][nt][e] + bias[cc];
                }
            }
        }
    }
}

// ---------------- LayerNorm fused with roll+window gather ----------------
__global__ void ln_kernel(const float* __restrict__ x, const float* __restrict__ g,
                          const float* __restrict__ b,
                          __half* __restrict__ ah, __half* __restrict__ al,
                          __half* __restrict__ xnp) {
    int p = blockIdx.x * 8 + (threadIdx.x >> 5);
    int lane = threadIdx.x & 31;
    const float* xr = x + (size_t)p * CDIM;
    float v[6];
    float s = 0.f;
#pragma unroll
    for (int k = 0; k < 6; k++) {
        int c = k * 32 + lane;
        v[k] = (c < CDIM) ? xr[c] : 0.f;
        s += v[k];
    }
    s = warp_sum(s);
    float mu = s * (1.0f / CDIM);
    float sq = 0.f;
#pragma unroll
    for (int k = 0; k < 6; k++) {
        int c = k * 32 + lane;
        if (c < CDIM) { float d = v[k] - mu; sq += d * d; }
    }
    sq = warp_sum(sq);
    float rstd = rsqrtf(sq * (1.0f / CDIM) + 1e-5f);
    int rr = p >> 8, cc = p & 255;
    int hs = (rr + 248) & 255, ws = (cc + 248) & 255;
    int widx = (((hs >> 4) << 4) + (ws >> 4)) * 256 + ((hs & 15) << 4) + (ws & 15);
    size_t aidx = (size_t)widx * KP1;
    size_t pidx = (size_t)((rr + 1) * PW + cc + 1) * KP1;
#pragma unroll
    for (int k = 0; k < 6; k++) {
        int c = k * 32 + lane;
        if (c < CDIM) {
            float y = (v[k] - mu) * rstd * g[c] + b[c];
            store_hilo(ah, al, aidx + c, y);
            xnp[pidx + c] = __float2half_rn(y);
        }
    }
}

// ---------------- channel attention pooling ----------------
__global__ void pool_kernel(const float* __restrict__ y2, float* __restrict__ casum) {
    int c = threadIdx.x;
    if (c >= CDIM) return;
    int p0 = blockIdx.x * 256;
    float s = 0.f;
    for (int i = 0; i < 256; i++) s += y2[(size_t)(p0 + i) * CDIM + c];
    atomicAdd(&casum[c], s);
}

__global__ void ca_kernel(const float* __restrict__ casum,
                          const float* __restrict__ w1, const float* __restrict__ b1,
                          const float* __restrict__ w2, const float* __restrict__ b2,
                          float* __restrict__ ca) {
    __shared__ float mean[CDIM];
    __shared__ float sq[6];
    int t = threadIdx.x;
    if (t < CDIM) mean[t] = casum[t] * (1.0f / NP);
    __syncthreads();
    if (t < 6) {
        float a = b1[t];
        for (int c = 0; c < CDIM; c++) a += mean[c] * w1[t * CDIM + c];
        sq[t] = fmaxf(a, 0.f);
    }
    __syncthreads();
    if (t < CDIM) {
        float a = b2[t];
#pragma unroll
        for (int s = 0; s < 6; s++) a += sq[s] * w2[t * 6 + s];
        ca[t] = 1.0f / (1.0f + __expf(-a));
    }
}

// ---------------- flash attention via mma.sync (block = window x head) ----------------
#define AQ_H 0
#define AQ_L 10240
#define AK_H 20480
#define AV_H 23040
#define ATTN_SMEM ((23040 + 32 * 72) * 2)

__global__ void __launch_bounds__(256, 1) attn_mma(
    const float* __restrict__ qkv,
    const __half* __restrict__ rpbb, const float* __restrict__ mask,
    __half* __restrict__ oh, __half* __restrict__ ol) {
    extern __shared__ __align__(16) __half smA[];
    const uint32_t smb = smem_u32(smA);
    const int win = blockIdx.x, head = blockIdx.y;
    const int tid = threadIdx.x, w = tid >> 5, lane = tid & 31;
    const int r_in = lane >> 2;
    const int a_row = lane & 15, a_koff = (lane >> 4) << 3;
    const int b_grp = lane >> 3, b_n = ((b_grp & 1) << 3) + (lane & 7), b_koff = (b_grp >> 1) << 3;
    const bool has_mask = ((win >> 4) == 15) || ((win & 15) == 15);

    {
        const float* qp = qkv + ((size_t)(win * 256 + tid)) * 540 + head * HD;
        __half* qh = smA + AQ_H + tid * 40;
        __half* ql = smA + AQ_L + tid * 40;
#pragma unroll
        for (int d = 0; d < 32; d++) {
            float v = (d < HD) ? qp[d] * 0.18257418583505536f : 0.f;
            __half h = __float2half_rn(v);
            qh[d] = h;
            ql[d] = __float2half_rn(v - __half2float(h));
        }
    }

    float accO[2][4][4] = {};
    float mrow[4] = { -1e30f, -1e30f, -1e30f, -1e30f };
    float lrow[4] = { 0.f, 0.f, 0.f, 0.f };

    const __half* rbbase = rpbb + (size_t)head * 65536;
    const float* mkbase = mask + (size_t)win * 65536;

    for (int chunk = 0; chunk < 4; chunk++) {
        const int kb = chunk * 64;
        __syncthreads();
        {
            int key = tid >> 2, dg = (tid & 3) * 8;
            const float* kp = qkv + ((size_t)(win * 256 + kb + key)) * 540 + 180 + head * HD;
            __half* kh = smA + AK_H + key * 40;
#pragma unroll
            for (int i = 0; i < 8; i++) {
                int d = dg + i;
                kh[d] = __float2half_rn((d < HD) ? kp[d] : 0.f);
            }
        }
        {
            int kp2 = (tid & 31) * 2;
            int d0 = tid >> 5;
            const float* vp0 = qkv + ((size_t)(win * 256 + kb + kp2)) * 540 + 360 + head * HD;
            const float* vp1 = vp0 + 540;
#pragma unroll
            for (int it = 0; it < 4; it++) {
                int d = d0 + it * 8;
                smA[AV_H + d * 72 + kp2] = __float2half_rn((d < HD) ? vp0[d] : 0.f);
                smA[AV_H + d * 72 + kp2 + 1] = __float2half_rn((d < HD) ? vp1[d] : 0.f);
            }
        }
        __syncthreads();

        float accS[2][8][4] = {};
#pragma unroll
        for (int pass = 0; pass < 2; pass++) {
            const uint32_t qB = smb + (pass ? AQ_L : AQ_H) * 2;
            const uint32_t kB = smb + AK_H * 2;
#pragma unroll
            for (int kk = 0; kk < 2; kk++) {
                uint32_t a[2][4], b[4][4];
#pragma unroll
                for (int mt = 0; mt < 2; mt++) {
                    uint32_t ad = qB + (uint32_t)((w * 32 + mt * 16 + a_row) * 80 +
                                                  (kk * 16 + a_koff) * 2);
                    ldsm_x4(a[mt][0], a[mt][1], a[mt][2], a[mt][3], ad);
                }
#pragma unroll
                for (int np = 0; np < 4; np++) {
                    uint32_t bd = kB + (uint32_t)((np * 16 + b_n) * 80 +
                                                  (kk * 16 + b_koff) * 2);
                    ldsm_x4(b[np][0], b[np][1], b[np][2], b[np][3], bd);
                }
#pragma unroll
                for (int mt = 0; mt < 2; mt++) {
#pragma unroll
                    for (int np = 0; np < 4; np++) {
                        uint32_t f0[2] = { b[np][0], b[np][2] };
                        uint32_t f1[2] = { b[np][1], b[np][3] };
                        mma_f16(accS[mt][2 * np + 0], a[mt], f0);
                        mma_f16(accS[mt][2 * np + 1], a[mt], f1);
                    }
                }
            }
        }

#pragma unroll
        for (int mt = 0; mt < 2; mt++) {
            int r0 = w * 32 + mt * 16 + r_in;
            const __half* rb0 = rbbase + (size_t)r0 * 256;
            const __half* rb1 = rb0 + 8 * 256;
#pragma unroll
            for (int nt = 0; nt < 8; nt++) {
                int colb = kb + nt * 8 + ((lane & 3) << 1);
                float2 rA = __half22float2(*(const __half2*)(rb0 + colb));
                float2 rB = __half22float2(*(const __half2*)(rb1 + colb));
                accS[mt][nt][0] += rA.x;
                accS[mt][nt][1] += rA.y;
                accS[mt][nt][2] += rB.x;
                accS[mt][nt][3] += rB.y;
            }
            if (has_mask) {
                const float* mk0 = mkbase + (size_t)r0 * 256;
                const float* mk1 = mk0 + 8 * 256;
#pragma unroll
                for (int nt = 0; nt < 8; nt++) {
                    int colb = kb + nt * 8 + ((lane & 3) << 1);
                    float2 mA = *(const float2*)(mk0 + colb);
                    float2 mB = *(const float2*)(mk1 + colb);
                    accS[mt][nt][0] += mA.x;
                    accS[mt][nt][1] += mA.y;
                    accS[mt][nt][2] += mB.x;
                    accS[mt][nt][3] += mB.y;
                }
            }
        }

        float corr[4];
#pragma unroll
        for (int s2 = 0; s2 < 4; s2++) {
            int mt = s2 >> 1, h = s2 & 1;
            float mx = -1e30f;
#pragma unroll
            for (int nt = 0; nt < 8; nt++) {
                mx = fmaxf(mx, fmaxf(accS[mt][nt][h * 2], accS[mt][nt][h * 2 + 1]));
            }
            mx = fmaxf(mx, __shfl_xor_sync(0xffffffffu, mx, 1));
            mx = fmaxf(mx, __shfl_xor_sync(0xffffffffu, mx, 2));
            float mnew = fmaxf(mrow[s2], mx);
            corr[s2] = __expf(mrow[s2] - mnew);
            mrow[s2] = mnew;
            float rs = 0.f;
#pragma unroll
            for (int nt = 0; nt < 8; nt++) {
                float p0 = __expf(accS[mt][nt][h * 2] - mnew);
                float p1 = __expf(accS[mt][nt][h * 2 + 1] - mnew);
                accS[mt][nt][h * 2] = p0;
                accS[mt][nt][h * 2 + 1] = p1;
                rs += p0 + p1;
            }
            rs += __shfl_xor_sync(0xffffffffu, rs, 1);
            rs += __shfl_xor_sync(0xffffffffu, rs, 2);
            lrow[s2] = lrow[s2] * corr[s2] + rs;
        }
#pragma unroll
        for (int mt = 0; mt < 2; mt++)
#pragma unroll
            for (int nt = 0; nt < 4; nt++)
#pragma unroll
                for (int e = 0; e < 4; e++)
                    accO[mt][nt][e] *= corr[mt * 2 + (e >> 1)];

#pragma unroll
        for (int kk = 0; kk < 4; kk++) {
            uint32_t phi[2][4], plo[2][4];
#pragma unroll
            for (int mt = 0; mt < 2; mt++) {
                int nt0 = 2 * kk, nt1 = 2 * kk + 1;
                split2(accS[mt][nt0][0], accS[mt][nt0][1], phi[mt][0], plo[mt][0]);
                split2(accS[mt][nt0][2], accS[mt][nt0][3], phi[mt][1], plo[mt][1]);
                split2(accS[mt][nt1][0], accS[mt][nt1][1], phi[mt][2], plo[mt][2]);
                split2(accS[mt][nt1][2], accS[mt][nt1][3], phi[mt][3], plo[mt][3]);
            }
            uint32_t bh[2][4];
#pragma unroll
            for (int np = 0; np < 2; np++) {
                uint32_t adh = smb + AV_H * 2 +
                    (uint32_t)((np * 16 + b_n) * 144 + (kk * 16 + b_koff) * 2);
                ldsm_x4(bh[np][0], bh[np][1], bh[np][2], bh[np][3], adh);
            }
#pragma unroll
            for (int mt = 0; mt < 2; mt++) {
#pragma unroll
                for (int np = 0; np < 2; np++) {
                    uint32_t h0[2] = { bh[np][0], bh[np][2] };
                    uint32_t h1[2] = { bh[np][1], bh[np][3] };
                    mma_f16(accO[mt][2 * np + 0], phi[mt], h0);
                    mma_f16(accO[mt][2 * np + 1], phi[mt], h1);
                    mma_f16(accO[mt][2 * np + 0], plo[mt], h0);
                    mma_f16(accO[mt][2 * np + 1], plo[mt], h1);
                }
            }
        }
    }

    float inv[4];
#pragma unroll
    for (int s2 = 0; s2 < 4; s2++) inv[s2] = 1.0f / lrow[s2];
#pragma unroll
    for (int mt = 0; mt < 2; mt++) {
#pragma unroll
        for (int nt = 0; nt < 4; nt++) {
            int dbase = nt * 8 + ((lane & 3) << 1);
#pragma unroll
            for (int e = 0; e < 4; e++) {
                int d = dbase + (e & 1);
                if (d < HD) {
                    int row = w * 32 + mt * 16 + r_in + ((e >> 1) << 3);
                    float v = accO[mt][nt][e] * inv[mt * 2 + (e >> 1)];
                    store_hilo(oh, ol, (size_t)(win * 256 + row) * KP1 + head * HD + d, v);
                }
            }
        }
    }
}

// ---------------- residual combine + LN2 ----------------
__global__ void combine_ln2(const float* __restrict__ x, const float* __restrict__ proj,
                            const float* __restrict__ y2, const float* __restrict__ ca,
                            const float* __restrict__ g2, const float* __restrict__ b2,
                            float* __restrict__ x1,
                            __half* __restrict__ mh, __half* __restrict__ ml) {
    int p = blockIdx.x * 8 + (threadIdx.x >> 5);
    int lane = threadIdx.x & 31;
    int r = p >> 8, cc = p & 255;
    int hs = (r + 248) & 255;
    int ws2 = (cc + 248) & 255;
    int widx = (((hs >> 4) << 4) + (ws2 >> 4)) * 256 + ((hs & 15) << 4) + (ws2 & 15);
    float v[6];
    float s = 0.f;
#pragma unroll
    for (int k = 0; k < 6; k++) {
        int c = k * 32 + lane;
        if (c < CDIM) {
            v[k] = x[(size_t)p * CDIM + c] + proj[(size_t)widx * CDIM + c]
                 + 0.01f * y2[(size_t)p * CDIM + c] * ca[c];
        } else v[k] = 0.f;
        s += v[k];
    }
    s = warp_sum(s);
    float mu = s * (1.0f / CDIM);
    float sq = 0.f;
#pragma unroll
    for (int k = 0; k < 6; k++) {
        int c = k * 32 + lane;
        if (c < CDIM) { float d = v[k] - mu; sq += d * d; }
    }
    sq = warp_sum(sq);
    float rstd = rsqrtf(sq * (1.0f / CDIM) + 1e-5f);
#pragma unroll
    for (int k = 0; k < 6; k++) {
        int c = k * 32 + lane;
        if (c < CDIM) {
            x1[(size_t)p * CDIM + c] = v[k];
            store_hilo(mh, ml, (size_t)p * KP1 + c, (v[k] - mu) * rstd * g2[c] + b2[c]);
        }
    }
}

// ---------------- launcher ----------------
extern "C" void kernel_launch(void* const* d_in, const int* in_sizes, int n_in,
                              void* d_out, int out_size) {
    const float* x     = (const float*)d_in[0];
    const int*   rpi   = (const int*)d_in[3];
    const float* mask  = (const float*)d_in[4];
    const float* n1g   = (const float*)d_in[5];
    const float* n1b   = (const float*)d_in[6];
    const float* qkvw  = (const float*)d_in[7];
    const float* qkvb  = (const float*)d_in[8];
    const float* rpbt  = (const float*)d_in[9];
    const float* projw = (const float*)d_in[10];
    const float* projb = (const float*)d_in[11];
    const float* c1w   = (const float*)d_in[12];
    const float* c1b   = (const float*)d_in[13];
    const float* c2w   = (const float*)d_in[14];
    const float* c2b   = (const float*)d_in[15];
    const float* ca1w  = (const float*)d_in[16];
    const float* ca1b  = (const float*)d_in[17];
    const float* ca2w  = (const float*)d_in[18];
    const float* ca2b  = (const float*)d_in[19];
    const float* n2g   = (const float*)d_in[20];
    const float* n2b   = (const float*)d_in[21];
    const float* f1w   = (const float*)d_in[22];
    const float* f1b   = (const float*)d_in[23];
    const float* f2w   = (const float*)d_in[24];
    const float* f2b   = (const float*)d_in[25];
    float* out = (float*)d_out;

    float *qkv, *proj, *y2, *casum, *ca, *x1;
    __half *rpbb, *xnp, *y1p, *ahi, *alo, *mhi, *mlo;
    __half *bqh, *bph, *b1h, *b2h, *wc1h, *wc2h;
    cudaGetSymbolAddress((void**)&qkv, g_qkv);
    cudaGetSymbolAddress((void**)&proj, g_proj);
    cudaGetSymbolAddress((void**)&y2, g_y2);
    cudaGetSymbolAddress((void**)&rpbb, g_rpbb);
    cudaGetSymbolAddress((void**)&casum, g_casum);
    cudaGetSymbolAddress((void**)&ca, g_ca);
    cudaGetSymbolAddress((void**)&x1, g_x1);
    cudaGetSymbolAddress((void**)&xnp, g_xnp);
    cudaGetSymbolAddress((void**)&y1p, g_y1p);
    cudaGetSymbolAddress((void**)&ahi, g_ahi);
    cudaGetSymbolAddress((void**)&alo, g_alo);
    cudaGetSymbolAddress((void**)&mhi, g_mhi);
    cudaGetSymbolAddress((void**)&mlo, g_mlo);
    cudaGetSymbolAddress((void**)&bqh, g_bqh);
    cudaGetSymbolAddress((void**)&bph, g_bph);
    cudaGetSymbolAddress((void**)&b1h, g_b1h);
    cudaGetSymbolAddress((void**)&b2h, g_b2h);
    cudaGetSymbolAddress((void**)&wc1h, g_wc1h);
    cudaGetSymbolAddress((void**)&wc2h, g_wc2h);

    cudaFuncSetAttribute(tc_gemm2<0>, cudaFuncAttributeMaxDynamicSharedMemorySize, G2_SMEM);
    cudaFuncSetAttribute(tc_gemm2<1>, cudaFuncAttributeMaxDynamicSharedMemorySize, G2_SMEM);
    cudaFuncSetAttribute(tc_mlp2, cudaFuncAttributeMaxDynamicSharedMemorySize, MLP_SMEM);
    cudaFuncSetAttribute(attn_mma, cudaFuncAttributeMaxDynamicSharedMemorySize, ATTN_SMEM);

    // single merged prep (weights, rpb, casum zero)
    mega_prep<<<2849, 256>>>(qkvw, projw, f1w, f2w, c1w, c2w, rpi, rpbt,
                             bqh, bph, b1h, b2h, wc1h, wc2h, rpbb, casum);
    ln_kernel<<<NP / 8, 256>>>(x, n1g, n1b, ahi, alo, xnp);

    // fork: conv branch on s2 (depends on ln output + mega_prep, both on legacy)
    cudaEventRecord(g_aux.ev0, 0);
    cudaStreamWaitEvent(g_aux.s2, g_aux.ev0, 0);
    conv1_tc<<<512, 256, 0, g_aux.s2>>>(xnp, wc1h, c1b, y1p);
    conv2_tc<<<dim3(3, 512), 256, 0, g_aux.s2>>>(y1p, wc2h, c2b, y2);
    pool_kernel<<<256, 192, 0, g_aux.s2>>>(y2, casum);
    ca_kernel<<<1, 192, 0, g_aux.s2>>>(casum, ca1w, ca1b, ca2w, ca2b, ca);
    cudaEventRecord(g_aux.ev1, g_aux.s2);

    // attention chain on legacy stream (concurrent with conv branch)
    tc_gemm2<0><<<512, 256, G2_SMEM>>>(ahi, alo, bqh, qkvb, qkv,
                                       nullptr, nullptr, 540, 540, 9);
    attn_mma<<<dim3(256, 6), 256, ATTN_SMEM>>>(qkv, rpbb, mask, ahi, alo);
    tc_gemm2<0><<<512, 256, G2_SMEM>>>(ahi, alo, bph, projb, proj,
                                       nullptr, nullptr, 180, 180, 3);

    // join conv branch, then combine + MLP
    cudaStreamWaitEvent(0, g_aux.ev1, 0);
    combine_ln2<<<NP / 8, 256>>>(x, proj, y2, ca, n2g, n2b, x1, ahi, alo);
    tc_gemm2<1><<<512, 256, G2_SMEM>>>(ahi, alo, b1h, f1b, nullptr, mhi, mlo,
                                       720, 768, 12);
    tc_mlp2<<<512, 256, MLP_SMEM>>>(mhi, mlo, b2h, f2b, x1, out);
}